// round 15
// baseline (speedup 1.0000x reference)
#include <cuda_runtime.h>

// x: (4096, 8192) fp32, row-major. p = x[:, :4096], q = x[:, 4096:].
// out[:, :4096] = p
// out[:, 4096:] = weight[row] * selu(p) + q
//
// block=512 (R9 optimum) + slab layout: each thread handles 2 float4-pairs
// in two coalesced slabs => 4 independent front-batched LDG.128 (MLP=4).
// Default cache policy everywhere (hints proven harmful in R4/R8).

#define SIZE   4096
#define HALF4  (SIZE / 4)          // 1024 float4 per half-row
#define ROW4   (2 * SIZE / 4)      // 2048 float4 per full x row
#define TOTAL4 (SIZE * HALF4)      // 4,194,304 float4-pairs

__device__ __forceinline__ float selu_f(float v) {
    const float SCALE = 1.0507009873554804934193349852946f;
    const float ALPHA = 1.6732632423543772848170429916717f;
    float neg = SCALE * ALPHA * (__expf(fminf(v, 0.0f)) - 1.0f);
    float pos = SCALE * v;
    return v > 0.0f ? pos : neg;
}

__device__ __forceinline__ float4 fuse4(float4 p, float4 q, float w) {
    float4 r;
    r.x = fmaf(w, selu_f(p.x), q.x);
    r.y = fmaf(w, selu_f(p.y), q.y);
    r.z = fmaf(w, selu_f(p.z), q.z);
    r.w = fmaf(w, selu_f(p.w), q.w);
    return r;
}

__global__ __launch_bounds__(512) void selu_fuse_kernel(
    const float4* __restrict__ x,
    const float*  __restrict__ weight,
    float4*       __restrict__ out)
{
    // Each block owns 1024 consecutive float4-pair indices, as two coalesced
    // 512-wide slabs so every warp's accesses stay contiguous 128B segments.
    int i0 = blockIdx.x * 1024 + threadIdx.x;
    int i1 = i0 + 512;

    int row0 = i0 >> 10, col0 = i0 & 1023;
    int row1 = i1 >> 10, col1 = i1 & 1023;

    long long off0 = (long long)row0 * ROW4 + col0;
    long long off1 = (long long)row1 * ROW4 + col1;

    // 4 independent 16B loads front-batched (MLP=4), default policy.
    float4 p0 = x[off0];
    float4 p1 = x[off1];
    float4 q0 = x[off0 + HALF4];
    float4 q1 = x[off1 + HALF4];

    float w0 = __ldg(weight + row0);
    float w1 = __ldg(weight + row1);

    float4 r0 = fuse4(p0, q0, w0);
    float4 r1 = fuse4(p1, q1, w1);

    out[off0]         = p0;
    out[off1]         = p1;
    out[off0 + HALF4] = r0;
    out[off1 + HALF4] = r1;
}

extern "C" void kernel_launch(void* const* d_in, const int* in_sizes, int n_in,
                              void* d_out, int out_size)
{
    const float4* x = (const float4*)d_in[0];
    const float*  w = (const float*)d_in[1];
    float4* out = (float4*)d_out;

    const int block = 512;
    const int grid  = TOTAL4 / (block * 2);   // 4096 blocks, 2 pairs/thread

    selu_fuse_kernel<<<grid, block>>>(x, w, out);
}

// round 16
// speedup vs baseline: 1.0205x; 1.0205x over previous
#include <cuda_runtime.h>

// FINAL (R9 reproduction — measured optimum).
//
// x: (4096, 8192) fp32, row-major. p = x[:, :4096], q = x[:, 4096:].
// out[:, :4096] = p
// out[:, 4096:] = weight[row] * selu(p) + q
//
// Structure: one float4-pair per thread, block=512, default cache policy.
// Exploration summary (kernel us / DRAM%):
//   this: 35.42/76.0 | block256: 35.74/75.4 | block1024: 35.94/76.0
//   slab MLP=4: 36.19/74.3 | ldcs: 36.93/72.6 | persistent: 37.82/71.8
//   256-bit ldg: 39.39/67.7
// Wall is pinned at ~43.5us = 268MB / 6.17 TB/s sustained — the HBM3e
// read/write-turnaround ceiling for a 1:1 rw mix on this chip.

#define SIZE   4096
#define HALF4  (SIZE / 4)          // 1024 float4 per half-row
#define ROWLEN (2 * SIZE)          // 8192 floats per x row

__device__ __forceinline__ float selu_f(float v) {
    const float SCALE = 1.0507009873554804934193349852946f;
    const float ALPHA = 1.6732632423543772848170429916717f;
    float neg = SCALE * ALPHA * (__expf(fminf(v, 0.0f)) - 1.0f);
    float pos = SCALE * v;
    return v > 0.0f ? pos : neg;
}

__global__ __launch_bounds__(512) void selu_fuse_kernel(
    const float4* __restrict__ x,
    const float*  __restrict__ weight,
    float4*       __restrict__ out)
{
    long long i = (long long)blockIdx.x * blockDim.x + threadIdx.x;

    int row  = (int)(i >> 10);          // i / 1024
    int col4 = (int)(i & 1023);         // i % 1024

    const float4* prow = x + (long long)row * (ROWLEN / 4);
    float4 p = prow[col4];
    float4 q = prow[col4 + HALF4];

    float w = __ldg(weight + row);

    float4 r;
    r.x = fmaf(w, selu_f(p.x), q.x);
    r.y = fmaf(w, selu_f(p.y), q.y);
    r.z = fmaf(w, selu_f(p.z), q.z);
    r.w = fmaf(w, selu_f(p.w), q.w);

    float4* orow = out + (long long)row * (ROWLEN / 4);
    orow[col4]         = p;   // pass-through first half
    orow[col4 + HALF4] = r;   // fused second half
}

extern "C" void kernel_launch(void* const* d_in, const int* in_sizes, int n_in,
                              void* d_out, int out_size)
{
    const float4* x = (const float4*)d_in[0];
    const float*  w = (const float*)d_in[1];
    float4* out = (float4*)d_out;

    const int total4 = SIZE * HALF4;        // 4,194,304 threads
    const int block = 512;
    const int grid  = total4 / block;       // 8192

    selu_fuse_kernel<<<grid, block>>>(x, w, out);
}